// round 15
// baseline (speedup 1.0000x reference)
#include <cuda_runtime.h>
#include <cuda_fp16.h>
#include <math.h>
#include <stdint.h>

// Problem constants
#define MROWS 4096   // B*T
#define CEMB  2048
#define TSEQ  2048
#define NHEAD 16
#define NGROUP 4
#define DHEAD 128
#define KVC   512
#define SWIN  512
#define SINK  4
#define NQKV  3072

// scratch (all fp16)
__device__ __half g_xh [(size_t)MROWS * CEMB];
__device__ __half g_oh [(size_t)MROWS * CEMB];
__device__ __half g_qh [(size_t)MROWS * CEMB];          // [b,h,t,d] pre-scaled
__device__ __half g_kh [(size_t)MROWS * KVC];           // [b,g,t,d]
__device__ __half g_vh [(size_t)MROWS * KVC];
__device__ __half g_WT [(size_t)NQKV * CEMB];           // packed Wq|Wk|Wv, [N,K]
__device__ __half g_WoT[(size_t)CEMB * CEMB];
__device__ float2 g_rope[(size_t)TSEQ * 64];

// ---------------------------------------------------------------------------
// helpers
// ---------------------------------------------------------------------------
__device__ __forceinline__ uint32_t cvta_s(const void* p) {
    return (uint32_t)__cvta_generic_to_shared(p);
}
__device__ __forceinline__ void cp16(uint32_t dst, const void* src) {
    asm volatile("cp.async.cg.shared.global [%0], [%1], 16;\n" :: "r"(dst), "l"(src));
}
#define CP_COMMIT() asm volatile("cp.async.commit_group;\n" ::: "memory")
#define CP_WAIT(n)  asm volatile("cp.async.wait_group %0;\n" :: "n"(n) : "memory")

#define LDSM4(r, addr) \
    asm volatile("ldmatrix.sync.aligned.m8n8.x4.shared.b16 {%0,%1,%2,%3}, [%4];" \
        : "=r"((r)[0]), "=r"((r)[1]), "=r"((r)[2]), "=r"((r)[3]) : "r"(addr))

#define LDSM4T(r, addr) \
    asm volatile("ldmatrix.sync.aligned.m8n8.x4.trans.shared.b16 {%0,%1,%2,%3}, [%4];" \
        : "=r"((r)[0]), "=r"((r)[1]), "=r"((r)[2]), "=r"((r)[3]) : "r"(addr))

#define MMA_H(c, a, b0, b1) \
    asm volatile("mma.sync.aligned.m16n8k16.row.col.f32.f16.f16.f32 " \
        "{%0,%1,%2,%3},{%4,%5,%6,%7},{%8,%9},{%0,%1,%2,%3};" \
        : "+f"((c)[0]), "+f"((c)[1]), "+f"((c)[2]), "+f"((c)[3]) \
        : "r"((a)[0]), "r"((a)[1]), "r"((a)[2]), "r"((a)[3]), "r"(b0), "r"(b1))

// 128B-row swizzled address (BK=64 GEMM tiles)
__device__ __forceinline__ uint32_t adrK(int r, int c) {
    return (uint32_t)(r * 128 + ((c ^ (r & 7)) << 4));
}
// 256B-row swizzled address (attention tiles)
__device__ __forceinline__ uint32_t adr128(int r, int c) {
    return (uint32_t)(r * 256 + ((c ^ (r & 7)) << 4));
}

// ---------------------------------------------------------------------------
// prep: rope table + x fp32->fp16
// ---------------------------------------------------------------------------
__global__ void prep(const float* __restrict__ x, __half* __restrict__ xh,
                     float2* __restrict__ tab)
{
    int bid = blockIdx.x;
    if (bid < 512) {
        int i = bid * 256 + threadIdx.x;
        int d = i & 63, t = i >> 6;
        float inv = powf(10000.f, -(float)d * (1.f / 64.f));
        float s, c;
        sincosf((float)t * inv, &s, &c);
        tab[i] = make_float2(c, s);
    } else {
        int i = (bid - 512) * 256 + threadIdx.x;
        float4 v = ((const float4*)x)[i];
        __half2* p = (__half2*)xh;
        p[i * 2 + 0] = __floats2half2_rn(v.x, v.y);
        p[i * 2 + 1] = __floats2half2_rn(v.z, v.w);
    }
}

// ---------------------------------------------------------------------------
// transpose QKV weights -> fp16 single (packed rows)
// ---------------------------------------------------------------------------
__global__ void tsplit_qkv(const float* __restrict__ Wq,
                           const float* __restrict__ Wk,
                           const float* __restrict__ Wv,
                           __half* __restrict__ hi)
{
    __shared__ float t[32][33];
    int bx = blockIdx.x, k0 = blockIdx.y * 32;
    const float* W; int N, n0, ro;
    if (bx < 64)      { W = Wq; N = 2048; n0 = bx * 32;        ro = 0; }
    else if (bx < 80) { W = Wk; N = 512;  n0 = (bx - 64) * 32; ro = 2048; }
    else              { W = Wv; N = 512;  n0 = (bx - 80) * 32; ro = 2560; }
    int tx = threadIdx.x, ty = threadIdx.y;
#pragma unroll
    for (int i = 0; i < 4; i++)
        t[ty + 8 * i][tx] = W[(size_t)(k0 + ty + 8 * i) * N + n0 + tx];
    __syncthreads();
#pragma unroll
    for (int i = 0; i < 4; i++)
        hi[(size_t)(ro + n0 + ty + 8 * i) * CEMB + k0 + tx] =
            __float2half_rn(t[tx][ty + 8 * i]);
}

// ---------------------------------------------------------------------------
// transpose Wo -> fp16 single
// ---------------------------------------------------------------------------
__global__ void tsplit_wo(const float* __restrict__ W, __half* __restrict__ hi)
{
    __shared__ float t[32][33];
    int n0 = blockIdx.x * 32, k0 = blockIdx.y * 32;
    int tx = threadIdx.x, ty = threadIdx.y;
#pragma unroll
    for (int i = 0; i < 4; i++)
        t[ty + 8 * i][tx] = W[(size_t)(k0 + ty + 8 * i) * CEMB + n0 + tx];
    __syncthreads();
#pragma unroll
    for (int i = 0; i < 4; i++)
        hi[(size_t)(n0 + ty + 8 * i) * CEMB + k0 + tx] =
            __float2half_rn(t[tx][ty + 8 * i]);
}

// ---------------------------------------------------------------------------
// QKV GEMM: BM=256, BN=128, BK=64, 3-stage, 8 warps (4m x 2n), warp 64x64.
// Stage: A 32KB @ +0, B 16KB @ +32768; stage stride 49152.
// Warp wn owns cols {wn*32+j*16} u {64+wn*32+(j-2)*16} (rope pairs in-thread).
// ---------------------------------------------------------------------------
__global__ __launch_bounds__(256, 1) void gemm_qkv(
    const __half* __restrict__ A, const __half* __restrict__ B,
    const float* __restrict__ bq, const float* __restrict__ bk,
    const float* __restrict__ bv,
    __half* __restrict__ qh, __half* __restrict__ kh, __half* __restrict__ vh,
    const float2* __restrict__ rope)
{
    constexpr int KD = 2048, NCHUNK = 32, STG = 49152;
    constexpr size_t GSTRIDE = (size_t)32 * KD;   // +32 rows
    extern __shared__ char dsm[];
    uint32_t sbase = (cvta_s(dsm) + 1023) & ~1023u;

    const int tid = threadIdx.x;
    const int wid = tid >> 5, lane = tid & 31;
    const int wm = wid >> 1, wn = wid & 1;        // 4 x 2
    const int m0 = blockIdx.y * 256, n0 = blockIdx.x * 128;

    const int r0_ = tid >> 3, c0_ = tid & 7;      // rows 0..31
    const uint32_t dst0 = adrK(r0_, c0_);
    const __half* pA = A + (size_t)(m0 + r0_) * KD + c0_ * 8;
    const __half* pB = B + (size_t)(n0 + r0_) * KD + c0_ * 8;

    const int arow = (lane & 7) + ((lane >> 3) & 1) * 8;
    const int acb  = lane >> 4;
    const int brow = (lane & 7) + (lane >> 4) * 8;
    const int bcb  = (lane >> 3) & 1;
    const int cbs  = (lane & 3) * 2;

    float acc[4][8][4];
#pragma unroll
    for (int i = 0; i < 4; i++)
#pragma unroll
        for (int j = 0; j < 8; j++) {
            acc[i][j][0] = 0.f; acc[i][j][1] = 0.f;
            acc[i][j][2] = 0.f; acc[i][j][3] = 0.f;
        }

#pragma unroll
    for (int ch = 0; ch < 2; ch++) {
        uint32_t st = sbase + ch * STG;
        int k0 = ch * 64;
#pragma unroll
        for (int p = 0; p < 8; p++)      // A: 256 rows
            cp16(st + dst0 + p * 4096, pA + p * GSTRIDE + k0);
#pragma unroll
        for (int p = 0; p < 4; p++)      // B: 128 rows
            cp16(st + 32768 + dst0 + p * 4096, pB + p * GSTRIDE + k0);
        CP_COMMIT();
    }

    for (int c = 0; c < NCHUNK; c++) {
        if (c + 1 < NCHUNK) { CP_WAIT(1); } else { CP_WAIT(0); }
        __syncthreads();
        if (c + 2 < NCHUNK) {
            int ch = c + 2;
            uint32_t st = sbase + (ch % 3) * STG;
            int k0 = ch * 64;
#pragma unroll
            for (int p = 0; p < 8; p++)
                cp16(st + dst0 + p * 4096, pA + p * GSTRIDE + k0);
#pragma unroll
            for (int p = 0; p < 4; p++)
                cp16(st + 32768 + dst0 + p * 4096, pB + p * GSTRIDE + k0);
            CP_COMMIT();
        }

        uint32_t st = sbase + (c % 3) * STG;
        uint32_t aB = st, bB = st + 32768;

#pragma unroll
        for (int ks = 0; ks < 4; ks++) {
            uint32_t ah[4][4], bh[4][4];
#pragma unroll
            for (int mt = 0; mt < 4; mt++)
                LDSM4(ah[mt], aB + adrK(wm * 64 + mt * 16 + arow, 2 * ks + acb));
#pragma unroll
            for (int j = 0; j < 4; j++) {
                int bj = (j < 2) ? (wn * 32 + j * 16) : (64 + wn * 32 + (j - 2) * 16);
                LDSM4(bh[j], bB + adrK(bj + brow, 2 * ks + bcb));
            }
#pragma unroll
            for (int mt = 0; mt < 4; mt++)
#pragma unroll
                for (int j = 0; j < 4; j++) {
                    MMA_H(acc[mt][2 * j],     ah[mt], bh[j][0], bh[j][1]);
                    MMA_H(acc[mt][2 * j + 1], ah[mt], bh[j][2], bh[j][3]);
                }
        }
    }

    // register-direct epilogue
    const float* bias = (n0 < 2048) ? bq + n0
                      : (n0 < 2560) ? bk + (n0 - 2048)
                                    : bv + (n0 - 2560);

    if (n0 < 2560) {
        const bool isQ = (n0 < 2048);
        const float qsc = isQ ? 0.08838834764831845f : 1.0f;
        const int hh = isQ ? (n0 >> 7) : ((n0 - 2048) >> 7);
        const int nh = isQ ? NHEAD : NGROUP;
        __half* Out = isQ ? qh : kh;
#pragma unroll
        for (int mt = 0; mt < 4; mt++) {
            int rg = m0 + wm * 64 + mt * 16 + (lane >> 2);
            int tr = rg & (TSEQ - 1);
            int bb = rg >> 11;
            size_t orow0 = ((size_t)(bb * nh + hh) * TSEQ + tr) * DHEAD;
            size_t orow1 = orow0 + 8 * DHEAD;
#pragma unroll
            for (int nt = 0; nt < 4; nt++) {
                int d0 = wn * 32 + (nt >> 1) * 16 + (nt & 1) * 8 + cbs;
                float bb1 = bias[d0],      bb2 = bias[d0 + 1];
                float bb3 = bias[d0 + 64], bb4 = bias[d0 + 65];
                float2 ca = rope[tr * 64 + d0], cb = rope[tr * 64 + d0 + 1];
                {
                    float x1a = acc[mt][nt][0] + bb1, x1b = acc[mt][nt][1] + bb2;
                    float x2a = acc[mt][nt + 4][0] + bb3, x2b = acc[mt][nt + 4][1] + bb4;
                    float y1a = (x1a * ca.x - x2a * ca.y) * qsc;
                    float y2a = (x1a * ca.y + x2a * ca.x) * qsc;
                    float y1b = (x1b * cb.x - x2b * cb.y) * qsc;
                    float y2b = (x1b * cb.y + x2b * cb.x) * qsc;
                    *(__half2*)(Out + orow0 + d0)      = __floats2half2_rn(y1a, y1b);
                    *(__half2*)(Out + orow0 + 64 + d0) = __floats2half2_rn(y2a, y2b);
                }
                {
                    float2 ca8 = rope[(tr + 8) * 64 + d0];
                    float2 cb8 = rope[(tr + 8) * 64 + d0 + 1];
                    float x1a = acc[mt][nt][2] + bb1, x1b = acc[mt][nt][3] + bb2;
                    float x2a = acc[mt][nt + 4][2] + bb3, x2b = acc[mt][nt + 4][3] + bb4;
                    float y1a = (x1a * ca8.x - x2a * ca8.y) * qsc;
                    float y2a = (x1a * ca8.y + x2a * ca8.x) * qsc;
                    float y1b = (x1b * cb8.x - x2b * cb8.y) * qsc;
                    float y2b = (x1b * cb8.y + x2b * cb8.x) * qsc;
                    *(__half2*)(Out + orow1 + d0)      = __floats2half2_rn(y1a, y1b);
                    *(__half2*)(Out + orow1 + 64 + d0) = __floats2half2_rn(y2a, y2b);
                }
            }
        }
    } else {
        const int g = (n0 - 2560) >> 7;
#pragma unroll
        for (int mt = 0; mt < 4; mt++) {
            int rg = m0 + wm * 64 + mt * 16 + (lane >> 2);
            int tr = rg & (TSEQ - 1);
            int bb = rg >> 11;
            size_t orow0 = ((size_t)(bb * NGROUP + g) * TSEQ + tr) * DHEAD;
            size_t orow1 = orow0 + 8 * DHEAD;
#pragma unroll
            for (int nt = 0; nt < 8; nt++) {
                int j = nt >> 1;
                int base = (j < 2) ? (wn * 32 + j * 16) : (64 + wn * 32 + (j - 2) * 16);
                int d0 = base + (nt & 1) * 8 + cbs;
                float bb1 = bias[d0], bb2 = bias[d0 + 1];
                *(__half2*)(vh + orow0 + d0) =
                    __floats2half2_rn(acc[mt][nt][0] + bb1, acc[mt][nt][1] + bb2);
                *(__half2*)(vh + orow1 + d0) =
                    __floats2half2_rn(acc[mt][nt][2] + bb1, acc[mt][nt][3] + bb2);
            }
        }
    }
}

// ---------------------------------------------------------------------------
// Wo GEMM: BM=256, BN=128, BK=64, 3-stage, 8 warps (4m x 2n), fp32 out.
// ---------------------------------------------------------------------------
__global__ __launch_bounds__(256, 1) void gemm_wo(
    const __half* __restrict__ A, const __half* __restrict__ B,
    const float* __restrict__ bias, float* __restrict__ C)
{
    constexpr int KD = 2048, NCHUNK = 32, STG = 49152;
    constexpr size_t GSTRIDE = (size_t)32 * KD;
    extern __shared__ char dsm[];
    uint32_t sbase = (cvta_s(dsm) + 1023) & ~1023u;

    const int tid = threadIdx.x;
    const int wid = tid >> 5, lane = tid & 31;
    const int wm = wid >> 1, wn = wid & 1;
    const int m0 = blockIdx.y * 256, n0 = blockIdx.x * 128;

    const int r0_ = tid >> 3, c0_ = tid & 7;
    const uint32_t dst0 = adrK(r0_, c0_);
    const __half* pA = A + (size_t)(m0 + r0_) * KD + c0_ * 8;
    const __half* pB = B + (size_t)(n0 + r0_) * KD + c0_ * 8;

    const int arow = (lane & 7) + ((lane >> 3) & 1) * 8;
    const int acb  = lane >> 4;
    const int brow = (lane & 7) + (lane >> 4) * 8;
    const int bcb  = (lane >> 3) & 1;

    float acc[4][8][4];
#pragma unroll
    for (int i = 0; i < 4; i++)
#pragma unroll
        for (int j = 0; j < 8; j++) {
            acc[i][j][0] = 0.f; acc[i][j][1] = 0.f;
            acc[i][j][2] = 0.f; acc[i][j][3] = 0.f;
        }

#pragma unroll
    for (int ch = 0; ch < 2; ch++) {
        uint32_t st = sbase + ch * STG;
        int k0 = ch * 64;
#pragma unroll
        for (int p = 0; p < 8; p++)
            cp16(st + dst0 + p * 4096, pA + p * GSTRIDE + k0);
#pragma unroll
        for (int p = 0; p < 4; p++)
            cp16(st + 32768 + dst0 + p * 4096, pB + p * GSTRIDE + k0);
        CP_COMMIT();
    }

    for (int c = 0; c < NCHUNK; c++) {
        if (c + 1 < NCHUNK) { CP_WAIT(1); } else { CP_WAIT(0); }
        __syncthreads();
        if (c + 2 < NCHUNK) {
            int ch = c + 2;
            uint32_t st = sbase + (ch % 3) * STG;
            int k0 = ch * 64;
#pragma unroll
            for (int p = 0; p < 8; p++)
                cp16(st + dst0 + p * 4096, pA + p * GSTRIDE + k0);
#pragma unroll
            for (int p = 0; p < 4; p++)
                cp16(st + 32768 + dst0 + p * 4096, pB + p * GSTRIDE + k0);
            CP_COMMIT();
        }

        uint32_t st = sbase + (c % 3) * STG;
        uint32_t aB = st, bB = st + 32768;

#pragma unroll
        for (int ks = 0; ks < 4; ks++) {
            uint32_t ah[4][4], bh[4][4];
#pragma unroll
            for (int mt = 0; mt < 4; mt++)
                LDSM4(ah[mt], aB + adrK(wm * 64 + mt * 16 + arow, 2 * ks + acb));
#pragma unroll
            for (int j = 0; j < 4; j++)
                LDSM4(bh[j], bB + adrK(wn * 64 + j * 16 + brow, 2 * ks + bcb));
#pragma unroll
            for (int mt = 0; mt < 4; mt++)
#pragma unroll
                for (int j = 0; j < 4; j++) {
                    MMA_H(acc[mt][2 * j],     ah[mt], bh[j][0], bh[j][1]);
                    MMA_H(acc[mt][2 * j + 1], ah[mt], bh[j][2], bh[j][3]);
                }
        }
    }

#pragma unroll
    for (int mt = 0; mt < 4; mt++) {
        int r0 = m0 + wm * 64 + mt * 16 + (lane >> 2);
#pragma unroll
        for (int nt = 0; nt < 8; nt++) {
            int cc = n0 + wn * 64 + (nt >> 1) * 16 + (nt & 1) * 8 + (lane & 3) * 2;
            float bb0 = bias[cc], bb1 = bias[cc + 1];
            float2 v0 = make_float2(acc[mt][nt][0] + bb0, acc[mt][nt][1] + bb1);
            float2 v1 = make_float2(acc[mt][nt][2] + bb0, acc[mt][nt][3] + bb1);
            *(float2*)(C + (size_t)r0 * CEMB + cc) = v0;
            *(float2*)(C + (size_t)(r0 + 8) * CEMB + cc) = v1;
        }
    }
}

// ---------------------------------------------------------------------------
// flash attention: QT=128, KT=64, 3-stage KV (unchanged from R13/R14)
// ---------------------------------------------------------------------------
__global__ __launch_bounds__(256, 1) void attn_mma(
    const __half* __restrict__ qh_g, const __half* __restrict__ kh_g,
    const __half* __restrict__ vh_g, __half* __restrict__ oh)
{
    extern __shared__ char sm[];
    uint32_t sb = (cvta_s(sm) + 1023) & ~1023u;
    const uint32_t sQ  = sb;
    const uint32_t sKV = sb + 32768;

    const int tid = threadIdx.x, w = tid >> 5, lane = tid & 31;
    const int b = blockIdx.y >> 4, h = blockIdx.y & 15, g = h >> 2;
    const int qs = blockIdx.x * 128;

    int t0 = qs - SWIN; if (t0 < 0) t0 = 0;
    const int sink = (t0 > 0) ? 1 : 0;
    const int ntiles = sink + (qs + 128 - t0) / 64;
    const size_t kvbase = (size_t)(b * NGROUP + g) * TSEQ * DHEAD;

    const int lr0 = tid >> 4, lc0 = tid & 15;
    const uint32_t ldst0 = adr128(lr0, lc0);
    const size_t goff0 = (size_t)lr0 * DHEAD + lc0 * 8;

    {
        size_t qb = ((size_t)(b * NHEAD + h) * TSEQ + qs) * DHEAD + goff0;
#pragma unroll
        for (int p = 0; p < 8; p++)
            cp16(sQ + ldst0 + p * 4096, qh_g + qb + p * (16 * DHEAD));
    }
    CP_COMMIT();

#pragma unroll
    for (int j = 0; j < 2; j++) {
        int ts = (sink && j == 0) ? 0 : t0 + (j - sink) * 64;
        uint32_t st = sKV + j * 32768;
        const __half* pk = kh_g + kvbase + (size_t)ts * DHEAD + goff0;
        const __half* pv = vh_g + kvbase + (size_t)ts * DHEAD + goff0;
#pragma unroll
        for (int p = 0; p < 4; p++) {
            cp16(st +     0 + ldst0 + p * 4096, pk + p * (16 * DHEAD));
            cp16(st + 16384 + ldst0 + p * 4096, pv + p * (16 * DHEAD));
        }
        CP_COMMIT();
    }

    const int arow = (lane & 7) + ((lane >> 3) & 1) * 8;
    const int acb  = lane >> 4;
    const int brow = (lane & 7) + (lane >> 4) * 8;
    const int bcb  = (lane >> 3) & 1;
    const int vr_i = ((lane >> 3) & 1) * 8 + (lane & 7);
    const int vc_i = lane >> 4;
    const int i0 = qs + w * 16 + (lane >> 2);
    const int i1 = i0 + 8;
    const int iwmin = qs + w * 16;
    const int iwmax = qs + w * 16 + 15;
    const int cbs = (lane & 3) * 2;

    CP_WAIT(2);
    __syncthreads();
    uint32_t qf[8][4];
#pragma unroll
    for (int kc = 0; kc < 8; kc++)
        LDSM4(qf[kc], sQ + adr128(w * 16 + arow, 2 * kc + acb));

    float o[16][4];
#pragma unroll
    for (int i = 0; i < 16; i++) { o[i][0] = 0.f; o[i][1] = 0.f; o[i][2] = 0.f; o[i][3] = 0.f; }
    float m0 = -1e30f, m1 = -1e30f, l0 = 0.f, l1 = 0.f;

    for (int it = 0; it < ntiles; it++) {
        const bool snk = (sink && it == 0);
        const int ts = snk ? 0 : t0 + (it - sink) * 64;
        const int n2max = snk ? 1 : 4;

        if (it + 1 < ntiles) { CP_WAIT(1); } else { CP_WAIT(0); }
        __syncthreads();

        if (it + 2 < ntiles) {
            int tsn = t0 + (it + 2 - sink) * 64;
            uint32_t st = sKV + ((it + 2) % 3) * 32768;
            const __half* pk = kh_g + kvbase + (size_t)tsn * DHEAD + goff0;
            const __half* pv = vh_g + kvbase + (size_t)tsn * DHEAD + goff0;
#pragma unroll
            for (int p = 0; p < 4; p++) {
                cp16(st +     0 + ldst0 + p * 4096, pk + p * (16 * DHEAD));
                cp16(st + 16384 + ldst0 + p * 4096, pv + p * (16 * DHEAD));
            }
            CP_COMMIT();
        }

        uint32_t stg = sKV + (it % 3) * 32768;
        uint32_t sK = stg, sV = stg + 16384;

        float sc[8][4];
#pragma unroll
        for (int i = 0; i < 8; i++) { sc[i][0] = 0.f; sc[i][1] = 0.f; sc[i][2] = 0.f; sc[i][3] = 0.f; }

        for (int n2 = 0; n2 < n2max; n2++) {
            if (ts + n2 * 16 > iwmax) break;
#pragma unroll
            for (int kc = 0; kc < 8; kc++) {
                uint32_t kf[4];
                LDSM4(kf, sK + adr128(n2 * 16 + brow, 2 * kc + bcb));
                MMA_H(sc[2 * n2],     qf[kc], kf[0], kf[1]);
                MMA_H(sc[2 * n2 + 1], qf[kc], kf[2], kf[3]);
            }
        }

        float rm0 = -1e30f, rm1 = -1e30f;
        const bool full = (!snk) && (ts + 63 <= iwmin) && (ts >= iwmax - SWIN);
        if (full) {
#pragma unroll
            for (int nt = 0; nt < 8; nt++) {
                rm0 = fmaxf(rm0, fmaxf(sc[nt][0], sc[nt][1]));
                rm1 = fmaxf(rm1, fmaxf(sc[nt][2], sc[nt][3]));
            }
        } else {
#pragma unroll
            for (int nt = 0; nt < 8; nt++) {
                int j0 = ts + nt * 8 + cbs, j1 = j0 + 1;
                sc[nt][0] = (j0 <= i0 && (j0 >= i0 - SWIN || j0 < SINK)) ? sc[nt][0] : -1e30f;
                sc[nt][1] = (j1 <= i0 && (j1 >= i0 - SWIN || j1 < SINK)) ? sc[nt][1] : -1e30f;
                sc[nt][2] = (j0 <= i1 && (j0 >= i1 - SWIN || j0 < SINK)) ? sc[nt][2] : -1e30f;
                sc[nt][3] = (j1 <= i1 && (j1 >= i1 - SWIN || j1 < SINK)) ? sc[nt][3] : -1e30f;
                rm0 = fmaxf(rm0, fmaxf(sc[nt][0], sc[nt][1]));
                rm1 = fmaxf(rm1, fmaxf(sc[nt][2], sc[nt][3]));
            }
        }
        rm0 = fmaxf(rm0, __shfl_xor_sync(0xffffffffu, rm0, 1));
        rm0 = fmaxf(rm0, __shfl_xor_sync(0xffffffffu, rm0, 2));
        rm1 = fmaxf(rm1, __shfl_xor_sync(0xffffffffu, rm1, 1));
        rm1 = fmaxf(rm1, __shfl_xor_sync(0xffffffffu, rm1, 2));
        float mn0 = fmaxf(m0, rm0), mn1 = fmaxf(m1, rm1);
        float c0 = __expf(m0 - mn0), c1 = __expf(m1 - mn1);
        m0 = mn0; m1 = mn1;

        if (c0 != 1.f || c1 != 1.f) {
#pragma unroll
            for (int nd = 0; nd < 16; nd++) {
                o[nd][0] *= c0; o[nd][1] *= c0; o[nd][2] *= c1; o[nd][3] *= c1;
            }
        }

        float rs0 = 0.f, rs1 = 0.f;
        for (int k2 = 0; k2 < n2max; k2++) {
            if (ts + k2 * 16 > iwmax) break;
            uint32_t aP[4];
#pragma unroll
            for (int q2 = 0; q2 < 2; q2++) {
                int nt = 2 * k2 + q2;
                float p00 = __expf(sc[nt][0] - mn0), p01 = __expf(sc[nt][1] - mn0);
                float p10 = __expf(sc[nt][2] - mn1), p11 = __expf(sc[nt][3] - mn1);
                rs0 += p00 + p01; rs1 += p10 + p11;
                __half2 h0v = __floats2half2_rn(p00, p01);
                __half2 h1v = __floats2half2_rn(p10, p11);
                aP[2 * q2]     = *(uint32_t*)&h0v;
                aP[2 * q2 + 1] = *(uint32_t*)&h1v;
            }
#pragma unroll
            for (int ndp = 0; ndp < 8; ndp++) {
                uint32_t bv[4];
                LDSM4T(bv, sV + adr128(k2 * 16 + vr_i, ndp * 2 + vc_i));
                MMA_H(o[ndp * 2],     aP, bv[0], bv[1]);
                MMA_H(o[ndp * 2 + 1], aP, bv[2], bv[3]);
            }
        }
        rs0 += __shfl_xor_sync(0xffffffffu, rs0, 1);
        rs0 += __shfl_xor_sync(0xffffffffu, rs0, 2);
        rs1 += __shfl_xor_sync(0xffffffffu, rs1, 1);
        rs1 += __shfl_xor_sync(0xffffffffu, rs1, 2);
        l0 = l0 * c0 + rs0;
        l1 = l1 * c1 + rs1;
    }

    float il0 = 1.f / l0, il1 = 1.f / l1;
    size_t or0 = (size_t)(b * TSEQ + qs + w * 16 + (lane >> 2)) * CEMB + h * DHEAD;
    size_t or1 = or0 + (size_t)8 * CEMB;
#pragma unroll
    for (int nd = 0; nd < 16; nd++) {
        int col = nd * 8 + cbs;
        *(__half2*)(oh + or0 + col) = __floats2half2_rn(o[nd][0] * il0, o[nd][1] * il0);
        *(__half2*)(oh + or1 + col) = __floats2half2_rn(o[nd][2] * il1, o[nd][3] * il1);
    }
}

// ---------------------------------------------------------------------------
extern "C" void kernel_launch(void* const* d_in, const int* in_sizes, int n_in,
                              void* d_out, int out_size)
{
    const float* x  = (const float*)d_in[0];
    const float* Wq = (const float*)d_in[1];
    const float* bq = (const float*)d_in[2];
    const float* Wk = (const float*)d_in[3];
    const float* bk = (const float*)d_in[4];
    const float* Wv = (const float*)d_in[5];
    const float* bv = (const float*)d_in[6];
    const float* Wo = (const float*)d_in[7];
    const float* bo = (const float*)d_in[8];
    float* out = (float*)d_out;

    __half *xh, *qh, *kh, *vh, *oh, *wt, *wot;
    float2* rope;
    cudaGetSymbolAddress((void**)&xh,  g_xh);
    cudaGetSymbolAddress((void**)&qh,  g_qh);
    cudaGetSymbolAddress((void**)&kh,  g_kh);
    cudaGetSymbolAddress((void**)&vh,  g_vh);
    cudaGetSymbolAddress((void**)&oh,  g_oh);
    cudaGetSymbolAddress((void**)&wt,  g_WT);
    cudaGetSymbolAddress((void**)&wot, g_WoT);
    cudaGetSymbolAddress((void**)&rope, g_rope);

    const int GEMM_SMEM = 148480;   // 3*48KB + align
    cudaFuncSetAttribute(gemm_qkv, cudaFuncAttributeMaxDynamicSharedMemorySize, GEMM_SMEM);
    cudaFuncSetAttribute(gemm_wo,  cudaFuncAttributeMaxDynamicSharedMemorySize, GEMM_SMEM);
    const int ATTN_SMEM = 132096;   // 32KB Q + 3*32KB KV + align
    cudaFuncSetAttribute(attn_mma, cudaFuncAttributeMaxDynamicSharedMemorySize, ATTN_SMEM);

    // (0) prep  (1) QKV weights  (2) Wo weights
    prep<<<512 + (MROWS * CEMB / 4) / 256, 256>>>(x, xh, rope);
    tsplit_qkv<<<dim3(96, 64), dim3(32, 8)>>>(Wq, Wk, Wv, wt);
    tsplit_wo<<<dim3(64, 64), dim3(32, 8)>>>(Wo, wot);

    // (3) fused QKV projection + rope + pack  ← ncu capture slot
    gemm_qkv<<<dim3(NQKV / 128, MROWS / 256), 256, GEMM_SMEM>>>(
        xh, wt, bq, bk, bv, qh, kh, vh, rope);

    // (4) flash attention
    attn_mma<<<dim3(TSEQ / 128, 2 * NHEAD), 256, ATTN_SMEM>>>(qh, kh, vh, oh);

    // (5) output projection
    gemm_wo<<<dim3(CEMB / 128, MROWS / 256), 256, GEMM_SMEM>>>(oh, wot, bo, out);
}

// round 17
// speedup vs baseline: 1.0566x; 1.0566x over previous
#include <cuda_runtime.h>
#include <cuda_fp16.h>
#include <math.h>
#include <stdint.h>

// Problem constants
#define MROWS 4096   // B*T
#define CEMB  2048
#define TSEQ  2048
#define NHEAD 16
#define NGROUP 4
#define DHEAD 128
#define KVC   512
#define SWIN  512
#define SINK  4
#define NQKV  3072

// scratch (all fp16)
__device__ __half g_xh [(size_t)MROWS * CEMB];
__device__ __half g_oh [(size_t)MROWS * CEMB];
__device__ __half g_qh [(size_t)MROWS * CEMB];          // [b,h,t,d] pre-scaled
__device__ __half g_kh [(size_t)MROWS * KVC];           // [b,g,t,d]
__device__ __half g_vh [(size_t)MROWS * KVC];
__device__ __half g_WT [(size_t)NQKV * CEMB];           // packed Wq|Wk|Wv, [N,K]
__device__ __half g_WoT[(size_t)CEMB * CEMB];
__device__ float2 g_rope[(size_t)TSEQ * 64];

// ---------------------------------------------------------------------------
// helpers
// ---------------------------------------------------------------------------
__device__ __forceinline__ uint32_t cvta_s(const void* p) {
    return (uint32_t)__cvta_generic_to_shared(p);
}
__device__ __forceinline__ void cp16(uint32_t dst, const void* src) {
    asm volatile("cp.async.cg.shared.global [%0], [%1], 16;\n" :: "r"(dst), "l"(src));
}
#define CP_COMMIT() asm volatile("cp.async.commit_group;\n" ::: "memory")
#define CP_WAIT(n)  asm volatile("cp.async.wait_group %0;\n" :: "n"(n) : "memory")

#define LDSM4(r, addr) \
    asm volatile("ldmatrix.sync.aligned.m8n8.x4.shared.b16 {%0,%1,%2,%3}, [%4];" \
        : "=r"((r)[0]), "=r"((r)[1]), "=r"((r)[2]), "=r"((r)[3]) : "r"(addr))

#define LDSM4T(r, addr) \
    asm volatile("ldmatrix.sync.aligned.m8n8.x4.trans.shared.b16 {%0,%1,%2,%3}, [%4];" \
        : "=r"((r)[0]), "=r"((r)[1]), "=r"((r)[2]), "=r"((r)[3]) : "r"(addr))

#define MMA_H(c, a, b0, b1) \
    asm volatile("mma.sync.aligned.m16n8k16.row.col.f32.f16.f16.f32 " \
        "{%0,%1,%2,%3},{%4,%5,%6,%7},{%8,%9},{%0,%1,%2,%3};" \
        : "+f"((c)[0]), "+f"((c)[1]), "+f"((c)[2]), "+f"((c)[3]) \
        : "r"((a)[0]), "r"((a)[1]), "r"((a)[2]), "r"((a)[3]), "r"(b0), "r"(b1))

// 128B-row swizzled address (BK=64 GEMM tiles): row r (0..127), 16B chunk c (0..7)
__device__ __forceinline__ uint32_t adrK(int r, int c) {
    return (uint32_t)(r * 128 + ((c ^ (r & 7)) << 4));
}
// 256B-row swizzled address (attention tiles): row r, 16B chunk c (0..15)
__device__ __forceinline__ uint32_t adr128(int r, int c) {
    return (uint32_t)(r * 256 + ((c ^ (r & 7)) << 4));
}

// ---------------------------------------------------------------------------
// prep_all: ONE launch for rope table + x convert + both weight transposes.
// blocks [0,512): rope  [512,8704): x conv  [8704,14848): Wqkv  [14848,18944): Wo
// ---------------------------------------------------------------------------
__global__ void prep_all(const float* __restrict__ x, __half* __restrict__ xh,
                         float2* __restrict__ tab,
                         const float* __restrict__ Wq, const float* __restrict__ Wk,
                         const float* __restrict__ Wv, __half* __restrict__ wt,
                         const float* __restrict__ Wo, __half* __restrict__ wot)
{
    __shared__ float t[32][33];
    const int bid = blockIdx.x, tid = threadIdx.x;

    if (bid < 512) {
        int i = bid * 256 + tid;
        int d = i & 63, tt = i >> 6;
        float inv = powf(10000.f, -(float)d * (1.f / 64.f));
        float s, c;
        sincosf((float)tt * inv, &s, &c);
        tab[i] = make_float2(c, s);
        return;
    }
    if (bid < 8704) {
        int i = (bid - 512) * 256 + tid;   // < MROWS*CEMB/4 = 2M
        float4 v = ((const float4*)x)[i];
        __half2* p = (__half2*)xh;
        p[i * 2 + 0] = __floats2half2_rn(v.x, v.y);
        p[i * 2 + 1] = __floats2half2_rn(v.z, v.w);
        return;
    }

    const int tx = tid & 31, ty = tid >> 5;
    if (bid < 14848) {
        int idx = bid - 8704;
        int bx = idx % 96, k0 = (idx / 96) * 32;
        const float* W; int N, n0, ro;
        if (bx < 64)      { W = Wq; N = 2048; n0 = bx * 32;        ro = 0; }
        else if (bx < 80) { W = Wk; N = 512;  n0 = (bx - 64) * 32; ro = 2048; }
        else              { W = Wv; N = 512;  n0 = (bx - 80) * 32; ro = 2560; }
#pragma unroll
        for (int i = 0; i < 4; i++)
            t[ty + 8 * i][tx] = W[(size_t)(k0 + ty + 8 * i) * N + n0 + tx];
        __syncthreads();
#pragma unroll
        for (int i = 0; i < 4; i++)
            wt[(size_t)(ro + n0 + ty + 8 * i) * CEMB + k0 + tx] =
                __float2half_rn(t[tx][ty + 8 * i]);
    } else {
        int idx = bid - 14848;
        int n0 = (idx % 64) * 32, k0 = (idx / 64) * 32;
#pragma unroll
        for (int i = 0; i < 4; i++)
            t[ty + 8 * i][tx] = Wo[(size_t)(k0 + ty + 8 * i) * CEMB + n0 + tx];
        __syncthreads();
#pragma unroll
        for (int i = 0; i < 4; i++)
            wot[(size_t)(n0 + ty + 8 * i) * CEMB + k0 + tx] =
                __float2half_rn(t[tx][ty + 8 * i]);
    }
}

// ---------------------------------------------------------------------------
// QKV GEMM (R13 best config): 1-term fp16, BK=64, 3-stage, const-offset.
// Permuted B mapping for register-direct rope epilogue.
// ---------------------------------------------------------------------------
__global__ __launch_bounds__(256, 2) void gemm_qkv(
    const __half* __restrict__ A, const __half* __restrict__ B,
    const float* __restrict__ bq, const float* __restrict__ bk,
    const float* __restrict__ bv,
    __half* __restrict__ qh, __half* __restrict__ kh, __half* __restrict__ vh,
    const float2* __restrict__ rope)
{
    constexpr int KD = 2048, NCHUNK = 32, STG = 32768;
    constexpr size_t GSTRIDE = (size_t)32 * KD;
    extern __shared__ char dsm[];
    uint32_t sbase = (cvta_s(dsm) + 1023) & ~1023u;

    const int tid = threadIdx.x;
    const int wid = tid >> 5, lane = tid & 31;
    const int wm = wid >> 2, wn = wid & 3;
    const int m0 = blockIdx.y * 128, n0 = blockIdx.x * 128;

    const int r0_ = tid >> 3, c0_ = tid & 7;
    const uint32_t dst0 = adrK(r0_, c0_);
    const __half* pA = A + (size_t)(m0 + r0_) * KD + c0_ * 8;
    const __half* pB = B + (size_t)(n0 + r0_) * KD + c0_ * 8;

    const int arow = (lane & 7) + ((lane >> 3) & 1) * 8;
    const int acb  = lane >> 4;
    const int brow = (lane & 7) + (lane >> 4) * 8;
    const int bcb  = (lane >> 3) & 1;
    const int cbs  = (lane & 3) * 2;

    float acc[4][4][4];
#pragma unroll
    for (int i = 0; i < 4; i++)
#pragma unroll
        for (int j = 0; j < 4; j++) {
            acc[i][j][0] = 0.f; acc[i][j][1] = 0.f;
            acc[i][j][2] = 0.f; acc[i][j][3] = 0.f;
        }

#pragma unroll
    for (int ch = 0; ch < 2; ch++) {
        uint32_t st = sbase + ch * STG;
        int k0 = ch * 64;
#pragma unroll
        for (int p = 0; p < 4; p++) {
            cp16(st +     0 + dst0 + p * 4096, pA + p * GSTRIDE + k0);
            cp16(st + 16384 + dst0 + p * 4096, pB + p * GSTRIDE + k0);
        }
        CP_COMMIT();
    }

    for (int c = 0; c < NCHUNK; c++) {
        if (c + 1 < NCHUNK) { CP_WAIT(1); } else { CP_WAIT(0); }
        __syncthreads();
        if (c + 2 < NCHUNK) {
            int ch = c + 2;
            uint32_t st = sbase + (ch % 3) * STG;
            int k0 = ch * 64;
#pragma unroll
            for (int p = 0; p < 4; p++) {
                cp16(st +     0 + dst0 + p * 4096, pA + p * GSTRIDE + k0);
                cp16(st + 16384 + dst0 + p * 4096, pB + p * GSTRIDE + k0);
            }
            CP_COMMIT();
        }

        uint32_t st = sbase + (c % 3) * STG;
        uint32_t aB = st, bB = st + 16384;

#pragma unroll
        for (int ks = 0; ks < 4; ks++) {
            uint32_t ah[4][4], bh[2][4];
#pragma unroll
            for (int mt = 0; mt < 4; mt++)
                LDSM4(ah[mt], aB + adrK(wm * 64 + mt * 16 + arow, 2 * ks + acb));
#pragma unroll
            for (int np = 0; np < 2; np++)
                LDSM4(bh[np], bB + adrK(wn * 16 + np * 64 + brow, 2 * ks + bcb));
#pragma unroll
            for (int mt = 0; mt < 4; mt++)
#pragma unroll
                for (int nt = 0; nt < 4; nt++)
                    MMA_H(acc[mt][nt], ah[mt], bh[nt >> 1][(nt & 1) * 2],
                          bh[nt >> 1][(nt & 1) * 2 + 1]);
        }
    }

    // register-direct epilogue
    const float* bias = (n0 < 2048) ? bq + n0
                      : (n0 < 2560) ? bk + (n0 - 2048)
                                    : bv + (n0 - 2560);

    if (n0 < 2560) {
        const bool isQ = (n0 < 2048);
        const float qsc = isQ ? 0.08838834764831845f : 1.0f;
        const int hh = isQ ? (n0 >> 7) : ((n0 - 2048) >> 7);
        const int nh = isQ ? NHEAD : NGROUP;
        __half* Out = isQ ? qh : kh;
#pragma unroll
        for (int mt = 0; mt < 4; mt++) {
            int rg = m0 + wm * 64 + mt * 16 + (lane >> 2);
            int tr = rg & (TSEQ - 1);
            int bb = rg >> 11;
            size_t orow0 = ((size_t)(bb * nh + hh) * TSEQ + tr) * DHEAD;
            size_t orow1 = orow0 + 8 * DHEAD;
#pragma unroll
            for (int nt = 0; nt < 2; nt++) {
                int d0 = wn * 16 + nt * 8 + cbs;
                float bb1 = bias[d0],      bb2 = bias[d0 + 1];
                float bb3 = bias[d0 + 64], bb4 = bias[d0 + 65];
                float2 ca = rope[tr * 64 + d0], cb = rope[tr * 64 + d0 + 1];
                {
                    float x1a = acc[mt][nt][0] + bb1, x1b = acc[mt][nt][1] + bb2;
                    float x2a = acc[mt][nt + 2][0] + bb3, x2b = acc[mt][nt + 2][1] + bb4;
                    float y1a = (x1a * ca.x - x2a * ca.y) * qsc;
                    float y2a = (x1a * ca.y + x2a * ca.x) * qsc;
                    float y1b = (x1b * cb.x - x2b * cb.y) * qsc;
                    float y2b = (x1b * cb.y + x2b * cb.x) * qsc;
                    *(__half2*)(Out + orow0 + d0)      = __floats2half2_rn(y1a, y1b);
                    *(__half2*)(Out + orow0 + 64 + d0) = __floats2half2_rn(y2a, y2b);
                }
                {
                    float2 ca8 = rope[(tr + 8) * 64 + d0];
                    float2 cb8 = rope[(tr + 8) * 64 + d0 + 1];
                    float x1a = acc[mt][nt][2] + bb1, x1b = acc[mt][nt][3] + bb2;
                    float x2a = acc[mt][nt + 2][2] + bb3, x2b = acc[mt][nt + 2][3] + bb4;
                    float y1a = (x1a * ca8.x - x2a * ca8.y) * qsc;
                    float y2a = (x1a * ca8.y + x2a * ca8.x) * qsc;
                    float y1b = (x1b * cb8.x - x2b * cb8.y) * qsc;
                    float y2b = (x1b * cb8.y + x2b * cb8.x) * qsc;
                    *(__half2*)(Out + orow1 + d0)      = __floats2half2_rn(y1a, y1b);
                    *(__half2*)(Out + orow1 + 64 + d0) = __floats2half2_rn(y2a, y2b);
                }
            }
        }
    } else {
        const int g = (n0 - 2560) >> 7;
#pragma unroll
        for (int mt = 0; mt < 4; mt++) {
            int rg = m0 + wm * 64 + mt * 16 + (lane >> 2);
            int tr = rg & (TSEQ - 1);
            int bb = rg >> 11;
            size_t orow0 = ((size_t)(bb * NGROUP + g) * TSEQ + tr) * DHEAD;
            size_t orow1 = orow0 + 8 * DHEAD;
#pragma unroll
            for (int nt = 0; nt < 4; nt++) {
                int d0 = wn * 16 + (nt >> 1) * 64 + (nt & 1) * 8 + cbs;
                float bb1 = bias[d0], bb2 = bias[d0 + 1];
                *(__half2*)(vh + orow0 + d0) =
                    __floats2half2_rn(acc[mt][nt][0] + bb1, acc[mt][nt][1] + bb2);
                *(__half2*)(vh + orow1 + d0) =
                    __floats2half2_rn(acc[mt][nt][2] + bb1, acc[mt][nt][3] + bb2);
            }
        }
    }
}

// ---------------------------------------------------------------------------
// Wo GEMM (R13 best config): 1-term fp16, BK=64, 3-stage, fp32 out.
// ---------------------------------------------------------------------------
__global__ __launch_bounds__(256, 2) void gemm_wo(
    const __half* __restrict__ A, const __half* __restrict__ B,
    const float* __restrict__ bias, float* __restrict__ C)
{
    constexpr int KD = 2048, NCHUNK = 32, STG = 32768;
    constexpr size_t GSTRIDE = (size_t)32 * KD;
    extern __shared__ char dsm[];
    uint32_t sbase = (cvta_s(dsm) + 1023) & ~1023u;

    const int tid = threadIdx.x;
    const int wid = tid >> 5, lane = tid & 31;
    const int wm = wid >> 2, wn = wid & 3;
    const int m0 = blockIdx.y * 128, n0 = blockIdx.x * 128;

    const int r0_ = tid >> 3, c0_ = tid & 7;
    const uint32_t dst0 = adrK(r0_, c0_);
    const __half* pA = A + (size_t)(m0 + r0_) * KD + c0_ * 8;
    const __half* pB = B + (size_t)(n0 + r0_) * KD + c0_ * 8;

    const int arow = (lane & 7) + ((lane >> 3) & 1) * 8;
    const int acb  = lane >> 4;
    const int brow = (lane & 7) + (lane >> 4) * 8;
    const int bcb  = (lane >> 3) & 1;

    float acc[4][4][4];
#pragma unroll
    for (int i = 0; i < 4; i++)
#pragma unroll
        for (int j = 0; j < 4; j++) {
            acc[i][j][0] = 0.f; acc[i][j][1] = 0.f;
            acc[i][j][2] = 0.f; acc[i][j][3] = 0.f;
        }

#pragma unroll
    for (int ch = 0; ch < 2; ch++) {
        uint32_t st = sbase + ch * STG;
        int k0 = ch * 64;
#pragma unroll
        for (int p = 0; p < 4; p++) {
            cp16(st +     0 + dst0 + p * 4096, pA + p * GSTRIDE + k0);
            cp16(st + 16384 + dst0 + p * 4096, pB + p * GSTRIDE + k0);
        }
        CP_COMMIT();
    }

    for (int c = 0; c < NCHUNK; c++) {
        if (c + 1 < NCHUNK) { CP_WAIT(1); } else { CP_WAIT(0); }
        __syncthreads();
        if (c + 2 < NCHUNK) {
            int ch = c + 2;
            uint32_t st = sbase + (ch % 3) * STG;
            int k0 = ch * 64;
#pragma unroll
            for (int p = 0; p < 4; p++) {
                cp16(st +     0 + dst0 + p * 4096, pA + p * GSTRIDE + k0);
                cp16(st + 16384 + dst0 + p * 4096, pB + p * GSTRIDE + k0);
            }
            CP_COMMIT();
        }

        uint32_t st = sbase + (c % 3) * STG;
        uint32_t aB = st, bB = st + 16384;

#pragma unroll
        for (int ks = 0; ks < 4; ks++) {
            uint32_t ah[4][4], bh[2][4];
#pragma unroll
            for (int mt = 0; mt < 4; mt++)
                LDSM4(ah[mt], aB + adrK(wm * 64 + mt * 16 + arow, 2 * ks + acb));
#pragma unroll
            for (int np = 0; np < 2; np++)
                LDSM4(bh[np], bB + adrK(wn * 32 + np * 16 + brow, 2 * ks + bcb));
#pragma unroll
            for (int mt = 0; mt < 4; mt++)
#pragma unroll
                for (int nt = 0; nt < 4; nt++)
                    MMA_H(acc[mt][nt], ah[mt], bh[nt >> 1][(nt & 1) * 2],
                          bh[nt >> 1][(nt & 1) * 2 + 1]);
        }
    }

#pragma unroll
    for (int mt = 0; mt < 4; mt++) {
        int r0 = m0 + wm * 64 + mt * 16 + (lane >> 2);
#pragma unroll
        for (int nt = 0; nt < 4; nt++) {
            int cc = n0 + wn * 32 + nt * 8 + (lane & 3) * 2;
            float bb0 = bias[cc], bb1 = bias[cc + 1];
            float2 v0 = make_float2(acc[mt][nt][0] + bb0, acc[mt][nt][1] + bb1);
            float2 v1 = make_float2(acc[mt][nt][2] + bb0, acc[mt][nt][3] + bb1);
            *(float2*)(C + (size_t)r0 * CEMB + cc) = v0;
            *(float2*)(C + (size_t)(r0 + 8) * CEMB + cc) = v1;
        }
    }
}

// ---------------------------------------------------------------------------
// flash attention: QT=128, KT=64, 3-stage KV. Grid: x=bh, y=qtile.
// ---------------------------------------------------------------------------
__global__ __launch_bounds__(256, 1) void attn_mma(
    const __half* __restrict__ qh_g, const __half* __restrict__ kh_g,
    const __half* __restrict__ vh_g, __half* __restrict__ oh)
{
    extern __shared__ char sm[];
    uint32_t sb = (cvta_s(sm) + 1023) & ~1023u;
    const uint32_t sQ  = sb;
    const uint32_t sKV = sb + 32768;

    const int tid = threadIdx.x, w = tid >> 5, lane = tid & 31;
    const int b = blockIdx.x >> 4, h = blockIdx.x & 15, g = h >> 2;
    const int qs = blockIdx.y * 128;

    int t0 = qs - SWIN; if (t0 < 0) t0 = 0;
    const int sink = (t0 > 0) ? 1 : 0;
    const int ntiles = sink + (qs + 128 - t0) / 64;
    const size_t kvbase = (size_t)(b * NGROUP + g) * TSEQ * DHEAD;

    const int lr0 = tid >> 4, lc0 = tid & 15;
    const uint32_t ldst0 = adr128(lr0, lc0);
    const size_t goff0 = (size_t)lr0 * DHEAD + lc0 * 8;

    {
        size_t qb = ((size_t)(b * NHEAD + h) * TSEQ + qs) * DHEAD + goff0;
#pragma unroll
        for (int p = 0; p < 8; p++)
            cp16(sQ + ldst0 + p * 4096, qh_g + qb + p * (16 * DHEAD));
    }
    CP_COMMIT();

#pragma unroll
    for (int j = 0; j < 2; j++) {
        int ts = (sink && j == 0) ? 0 : t0 + (j - sink) * 64;
        uint32_t st = sKV + j * 32768;
        const __half* pk = kh_g + kvbase + (size_t)ts * DHEAD + goff0;
        const __half* pv = vh_g + kvbase + (size_t)ts * DHEAD + goff0;
#pragma unroll
        for (int p = 0; p < 4; p++) {
            cp16(st +     0 + ldst0 + p * 4096, pk + p * (16 * DHEAD));
            cp16(st + 16384 + ldst0 + p * 4096, pv + p * (16 * DHEAD));
        }
        CP_COMMIT();
    }

    const int arow = (lane & 7) + ((lane >> 3) & 1) * 8;
    const int acb  = lane >> 4;
    const int brow = (lane & 7) + (lane >> 4) * 8;
    const int bcb  = (lane >> 3) & 1;
    const int vr_i = ((lane >> 3) & 1) * 8 + (lane & 7);
    const int vc_i = lane >> 4;
    const int i0 = qs + w * 16 + (lane >> 2);
    const int i1 = i0 + 8;
    const int iwmin = qs + w * 16;
    const int iwmax = qs + w * 16 + 15;
    const int cbs = (lane & 3) * 2;

    CP_WAIT(2);
    __syncthreads();
    uint32_t qf[8][4];
#pragma unroll
    for (int kc = 0; kc < 8; kc++)
        LDSM4(qf[kc], sQ + adr128(w * 16 + arow, 2 * kc + acb));

    float o[16][4];
#pragma unroll
    for (int i = 0; i < 16; i++) { o[i][0] = 0.f; o[i][1] = 0.f; o[i][2] = 0.f; o[i][3] = 0.f; }
    float m0 = -1e30f, m1 = -1e30f, l0 = 0.f, l1 = 0.f;

    for (int it = 0; it < ntiles; it++) {
        const bool snk = (sink && it == 0);
        const int ts = snk ? 0 : t0 + (it - sink) * 64;
        const int n2max = snk ? 1 : 4;

        if (it + 1 < ntiles) { CP_WAIT(1); } else { CP_WAIT(0); }
        __syncthreads();

        if (it + 2 < ntiles) {
            int tsn = t0 + (it + 2 - sink) * 64;
            uint32_t st = sKV + ((it + 2) % 3) * 32768;
            const __half* pk = kh_g + kvbase + (size_t)tsn * DHEAD + goff0;
            const __half* pv = vh_g + kvbase + (size_t)tsn * DHEAD + goff0;
#pragma unroll
            for (int p = 0; p < 4; p++) {
                cp16(st +     0 + ldst0 + p * 4096, pk + p * (16 * DHEAD));
                cp16(st + 16384 + ldst0 + p * 4096, pv + p * (16 * DHEAD));
            }
            CP_COMMIT();
        }

        uint32_t stg = sKV + (it % 3) * 32768;
        uint32_t sK = stg, sV = stg + 16384;

        float sc[8][4];
#pragma unroll
        for (int i = 0; i < 8; i++) { sc[i][0] = 0.f; sc[i][1] = 0.f; sc[i][2] = 0.f; sc[i][3] = 0.f; }

        for (int n2 = 0; n2 < n2max; n2++) {
            if (ts + n2 * 16 > iwmax) break;
#pragma unroll
            for (int kc = 0; kc < 8; kc++) {
                uint32_t kf[4];
                LDSM4(kf, sK + adr128(n2 * 16 + brow, 2 * kc + bcb));
                MMA_H(sc[2 * n2],     qf[kc], kf[0], kf[1]);
                MMA_H(sc[2 * n2 + 1], qf[kc], kf[2], kf[3]);
            }
        }

        float rm0 = -1e30f, rm1 = -1e30f;
        const bool full = (!snk) && (ts + 63 <= iwmin) && (ts >= iwmax - SWIN);
        if (full) {
#pragma unroll
            for (int nt = 0; nt < 8; nt++) {
                rm0 = fmaxf(rm0, fmaxf(sc[nt][0], sc[nt][1]));
                rm1 = fmaxf(rm1, fmaxf(sc[nt][2], sc[nt][3]));
            }
        } else {
#pragma unroll
            for (int nt = 0; nt < 8; nt++) {
                int j0 = ts + nt * 8 + cbs, j1 = j0 + 1;
                sc[nt][0] = (j0 <= i0 && (j0 >= i0 - SWIN || j0 < SINK)) ? sc[nt][0] : -1e30f;
                sc[nt][1] = (j1 <= i0 && (j1 >= i0 - SWIN || j1 < SINK)) ? sc[nt][1] : -1e30f;
                sc[nt][2] = (j0 <= i1 && (j0 >= i1 - SWIN || j0 < SINK)) ? sc[nt][2] : -1e30f;
                sc[nt][3] = (j1 <= i1 && (j1 >= i1 - SWIN || j1 < SINK)) ? sc[nt][3] : -1e30f;
                rm0 = fmaxf(rm0, fmaxf(sc[nt][0], sc[nt][1]));
                rm1 = fmaxf(rm1, fmaxf(sc[nt][2], sc[nt][3]));
            }
        }
        rm0 = fmaxf(rm0, __shfl_xor_sync(0xffffffffu, rm0, 1));
        rm0 = fmaxf(rm0, __shfl_xor_sync(0xffffffffu, rm0, 2));
        rm1 = fmaxf(rm1, __shfl_xor_sync(0xffffffffu, rm1, 1));
        rm1 = fmaxf(rm1, __shfl_xor_sync(0xffffffffu, rm1, 2));
        float mn0 = fmaxf(m0, rm0), mn1 = fmaxf(m1, rm1);
        float c0 = __expf(m0 - mn0), c1 = __expf(m1 - mn1);
        m0 = mn0; m1 = mn1;

        if (c0 != 1.f || c1 != 1.f) {
#pragma unroll
            for (int nd = 0; nd < 16; nd++) {
                o[nd][0] *= c0; o[nd][1] *= c0; o[nd][2] *= c1; o[nd][3] *= c1;
            }
        }

        float rs0 = 0.f, rs1 = 0.f;
        for (int k2 = 0; k2 < n2max; k2++) {
            if (ts + k2 * 16 > iwmax) break;
            uint32_t aP[4];
#pragma unroll
            for (int q2 = 0; q2 < 2; q2++) {
                int nt = 2 * k2 + q2;
                float p00 = __expf(sc[nt][0] - mn0), p01 = __expf(sc[nt][1] - mn0);
                float p10 = __expf(sc[nt][2] - mn1), p11 = __expf(sc[nt][3] - mn1);
                rs0 += p00 + p01; rs1 += p10 + p11;
                __half2 h0v = __floats2half2_rn(p00, p01);
                __half2 h1v = __floats2half2_rn(p10, p11);
                aP[2 * q2]     = *(uint32_t*)&h0v;
                aP[2 * q2 + 1] = *(uint32_t*)&h1v;
            }
#pragma unroll
            for (int ndp = 0; ndp < 8; ndp++) {
                uint32_t bv[4];
                LDSM4T(bv, sV + adr128(k2 * 16 + vr_i, ndp * 2 + vc_i));
                MMA_H(o[ndp * 2],     aP, bv[0], bv[1]);
                MMA_H(o[ndp * 2 + 1], aP, bv[2], bv[3]);
            }
        }
        rs0 += __shfl_xor_sync(0xffffffffu, rs0, 1);
        rs0 += __shfl_xor_sync(0xffffffffu, rs0, 2);
        rs1 += __shfl_xor_sync(0xffffffffu, rs1, 1);
        rs1 += __shfl_xor_sync(0xffffffffu, rs1, 2);
        l0 = l0 * c0 + rs0;
        l1 = l1 * c1 + rs1;
    }

    float il0 = 1.f / l0, il1 = 1.f / l1;
    size_t or0 = (size_t)(b * TSEQ + qs + w * 16 + (lane >> 2)) * CEMB + h * DHEAD;
    size_t or1 = or0 + (size_t)8 * CEMB;
#pragma unroll
    for (int nd = 0; nd < 16; nd++) {
        int col = nd * 8 + cbs;
        *(__half2*)(oh + or0 + col) = __floats2half2_rn(o[nd][0] * il0, o[nd][1] * il0);
        *(__half2*)(oh + or1 + col) = __floats2half2_rn(o[nd][2] * il1, o[nd][3] * il1);
    }
}

// ---------------------------------------------------------------------------
extern "C" void kernel_launch(void* const* d_in, const int* in_sizes, int n_in,
                              void* d_out, int out_size)
{
    const float* x  = (const float*)d_in[0];
    const float* Wq = (const float*)d_in[1];
    const float* bq = (const float*)d_in[2];
    const float* Wk = (const float*)d_in[3];
    const float* bk = (const float*)d_in[4];
    const float* Wv = (const float*)d_in[5];
    const float* bv = (const float*)d_in[6];
    const float* Wo = (const float*)d_in[7];
    const float* bo = (const float*)d_in[8];
    float* out = (float*)d_out;

    __half *xh, *qh, *kh, *vh, *oh, *wt, *wot;
    float2* rope;
    cudaGetSymbolAddress((void**)&xh,  g_xh);
    cudaGetSymbolAddress((void**)&qh,  g_qh);
    cudaGetSymbolAddress((void**)&kh,  g_kh);
    cudaGetSymbolAddress((void**)&vh,  g_vh);
    cudaGetSymbolAddress((void**)&oh,  g_oh);
    cudaGetSymbolAddress((void**)&wt,  g_WT);
    cudaGetSymbolAddress((void**)&wot, g_WoT);
    cudaGetSymbolAddress((void**)&rope, g_rope);

    const int GEMM_SMEM = 99328;    // 3*32KB + align
    cudaFuncSetAttribute(gemm_qkv, cudaFuncAttributeMaxDynamicSharedMemorySize, GEMM_SMEM);
    cudaFuncSetAttribute(gemm_wo,  cudaFuncAttributeMaxDynamicSharedMemorySize, GEMM_SMEM);
    const int ATTN_SMEM = 132096;   // 32KB Q + 3*32KB KV + align
    cudaFuncSetAttribute(attn_mma, cudaFuncAttributeMaxDynamicSharedMemorySize, ATTN_SMEM);

    // (0) all prep in one launch: 512 rope + 8192 conv + 6144 Wqkv + 4096 Wo
    prep_all<<<18944, 256>>>(x, xh, rope, Wq, Wk, Wv, wt, Wo, wot);

    // (1) fused QKV projection + rope + pack
    gemm_qkv<<<dim3(NQKV / 128, MROWS / 128), 256, GEMM_SMEM>>>(
        xh, wt, bq, bk, bv, qh, kh, vh, rope);

    // (2) flash attention (x=bh, y=qtile for KV L2 locality)
    attn_mma<<<dim3(2 * NHEAD, TSEQ / 128), 256, ATTN_SMEM>>>(qh, kh, vh, oh);

    // (3) output projection
    gemm_wo<<<dim3(CEMB / 128, MROWS / 128), 256, GEMM_SMEM>>>(oh, wot, bo, out);
}